// round 11
// baseline (speedup 1.0000x reference)
#include <cuda_runtime.h>
#include <cuda_fp16.h>
#include <cstdint>

// Problem constants
#define NB   16
#define CC   128
#define HH   112
#define WW   112
#define PLANE (HH*WW)          // 12544 pixels
#define PP   98
#define PTS  (PP*256)          // 25088 points per image

// 51.4 MB scratch: per pixel a 256B row of 64 half2 (channel-pair) values,
// stored in interleaved order: half2 position q holds channel pair
// P = (q>>2) + 16*(q&3)  <=>  q = 4*(P&15) + (P>>4).
// So the 16B chunk k (uint4) of a row holds pairs {k, k+16, k+32, k+48}.
__device__ uint2 g_nhwc[(size_t)NB * PLANE * 32];

union H2U { __half2 h; unsigned int u; };

// ---------------- Kernel 1: NCHW f32 -> interleaved NHWC fp16 ----------------
__global__ __launch_bounds__(256, 6)
void transpose_kernel(const float* __restrict__ fm)
{
    __shared__ __half2 sm[64][133];   // [q][px], padded rows (34 KB)
    const int n   = blockIdx.y;
    const int px0 = blockIdx.x * 128;
    const int t   = threadIdx.x;
    const int px  = t & 127;
    const int Pb  = t >> 7;           // 0/1

    const float* __restrict__ f0 = fm + (size_t)n * CC * PLANE + px0 + px;
    #pragma unroll 4
    for (int P = Pb; P < 64; P += 2) {
        const float a = f0[(size_t)(2 * P) * PLANE];       // coalesced
        const float b = f0[(size_t)(2 * P + 1) * PLANE];
        const int q = 4 * (P & 15) + (P >> 4);
        sm[q][px] = __floats2half2_rn(a, b);               // px-consecutive: conflict-free
    }
    __syncthreads();

    const int wid = t >> 5, l = t & 31;
    #pragma unroll 4
    for (int it = 0; it < 16; it++) {
        const int pxw = wid + 8 * it;                      // 0..127
        H2U v0, v1;
        v0.h = sm[2 * l][pxw];
        v1.h = sm[2 * l + 1][pxw];
        // warp writes 32 consecutive uint2 = 256B, fully coalesced
        g_nhwc[((size_t)n * PLANE + px0 + pxw) * 32 + l] = make_uint2(v0.u, v1.u);
    }
}

// ---------------- Kernel 2: sample (half-warp per point, all 128 ch) ----------
__global__ __launch_bounds__(256, 6)
void sample_kernel(const float* __restrict__ grid, float* __restrict__ out)
{
    __shared__ __half2 so[64][66];    // [P][px-in-tile], 16.9 KB
    const int b    = blockIdx.x;
    const int n    = b / PP;
    const int p    = b % PP;
    const int t    = threadIdx.x;
    const int wid  = t >> 5;
    const int lane = t & 31;
    const int sub  = lane >> 4;       // which of the 2 points in this warp
    const int k    = lane & 15;       // 16B chunk index -> pairs {k,k+16,k+32,k+48}

    const float2* __restrict__ g2 =
        (const float2*)grid + (size_t)n * PTS + p * 256;
    const uint4* __restrict__ nb =
        ((const uint4*)g_nhwc) + (size_t)n * PLANE * 16;
    float* __restrict__ ob = out + ((size_t)(n * PP + p) * CC) * 256;

    const int wpx = t & 63;           // write-phase pixel
    const int wPb = t >> 6;           // write-phase P base (0..3)

    for (int tile = 0; tile < 4; tile++) {
        // ---- gather: 64 points, 16 per sweep (2 per warp) ----
        #pragma unroll
        for (int sw = 0; sw < 4; sw++) {
            const int pixl = sw * 16 + wid * 2 + sub;      // 0..63
            const float2 xy = g2[tile * 64 + pixl];        // half-warp broadcast

            float x = fminf(fmaxf(fmaf(xy.x + 1.0f, 56.0f, -0.5f), 0.0f), 111.0f);
            float y = fminf(fmaxf(fmaf(xy.y + 1.0f, 56.0f, -0.5f), 0.0f), 111.0f);
            const int x0 = min((int)x, WW - 2);
            const int y0 = min((int)y, HH - 2);
            const float wx = x - (float)x0;
            const float wy = y - (float)y0;

            const size_t base = (size_t)(y0 * WW + x0) * 16 + k;
            const uint4 a0 = nb[base];                     // (y0,x0): 256B/half-warp
            const uint4 a1 = nb[base + 16];                // (y0,x1)
            const uint4 b0 = nb[base + 112 * 16];          // (y1,x0)
            const uint4 b1 = nb[base + 113 * 16];          // (y1,x1)

            const __half2 wx2 = __float2half2_rn(wx);
            const __half2 wy2 = __float2half2_rn(wy);

            const __half2* A0 = (const __half2*)&a0;
            const __half2* A1 = (const __half2*)&a1;
            const __half2* B0 = (const __half2*)&b0;
            const __half2* B1 = (const __half2*)&b1;

            #pragma unroll
            for (int j = 0; j < 4; j++) {
                const __half2 top = __hfma2(wx2, __hsub2(A1[j], A0[j]), A0[j]);
                const __half2 bot = __hfma2(wx2, __hsub2(B1[j], B0[j]), B0[j]);
                const __half2 res = __hfma2(wy2, __hsub2(bot, top), top);
                // P = k + 16j; bank = (2k + pixl) % 32 -> conflict-free
                so[k + 16 * j][pixl] = res;
            }
        }
        __syncthreads();

        // ---- write: 128 ch x 64 px, coalesced ----
        #pragma unroll
        for (int i = 0; i < 16; i++) {
            const int P = wPb + 4 * i;                     // 0..63
            const float2 f = __half22float2(so[P][wpx]);   // conflict-free
            float* o = ob + (2 * P) * 256 + tile * 64 + wpx;
            o[0]   = f.x;                                  // channel 2P
            o[256] = f.y;                                  // channel 2P+1
        }
        __syncthreads();
    }
}

extern "C" void kernel_launch(void* const* d_in, const int* in_sizes, int n_in,
                              void* d_out, int out_size)
{
    const float* fm   = (const float*)d_in[0];   // [16,128,112,112] f32
    const float* grid = (const float*)d_in[1];   // [16,98,16,16,2]  f32
    float* out        = (float*)d_out;           // [16,98,128,16,16] f32

    transpose_kernel<<<dim3(98, 16), 256>>>(fm);
    sample_kernel<<<NB * PP, 256>>>(grid, out);
}

// round 12
// speedup vs baseline: 1.2785x; 1.2785x over previous
#include <cuda_runtime.h>
#include <cuda_fp16.h>
#include <cstdint>

// Problem constants
#define NB   16
#define CC   128
#define HH   112
#define WW   112
#define PLANE (HH*WW)          // 12544 pixels per plane
#define PTS   (98*16*16)       // 25088 sample points per image
#define THREADS 512
#define PAIR_ITERS 24          // 24*1024 = 24576 points; tail = 512 points

static __device__ __forceinline__ unsigned int h2_bits(__half2 h)
{
    union { __half2 h; unsigned int u; } cvt;
    cvt.h = h;
    return cvt.u;
}

static __device__ __forceinline__ __half2 bilerp_h2(const __half2* __restrict__ s,
                                                    float x, float y)
{
    const int x0 = min((int)x, WW - 2);
    const int y0 = min((int)y, HH - 2);
    const float wx = x - (float)x0;
    const float wy = y - (float)y0;
    const int b00 = y0 * WW + x0;

    const __half2 q00 = s[b00];
    const __half2 q01 = s[b00 + 1];
    const __half2 q10 = s[b00 + WW];
    const __half2 q11 = s[b00 + WW + 1];

    const __half2 wx2 = __float2half2_rn(wx);
    const __half2 wy2 = __float2half2_rn(wy);
    const __half2 top = __hfma2(wx2, __hsub2(q01, q00), q00);
    const __half2 bot = __hfma2(wx2, __hsub2(q11, q10), q10);
    return __hfma2(wy2, __hsub2(bot, top), top);
}

static __device__ __forceinline__ float unnx(float v)
{
    return fminf(fmaxf(fmaf(v + 1.0f, 56.0f, -0.5f), 0.0f), 111.0f);
}

// smem: one half2 per pixel packing channels (c0, c0+1) -> 50,176 B
__global__ __launch_bounds__(THREADS, 3)
void patches_kernel(const float* __restrict__ fm,
                    const float* __restrict__ grid,
                    float* __restrict__ out)
{
    extern __shared__ __half2 s[];   // PLANE half2

    const int n  = blockIdx.x >> 6;          // 16 images
    const int c0 = (blockIdx.x & 63) * 2;    // 64 channel pairs

    // ---- Stage 2 channel planes packed as half2 (LDG.128 x2 + STS.128) ----
    {
        const float4* __restrict__ pa =
            reinterpret_cast<const float4*>(fm + ((size_t)n * CC + c0) * PLANE);
        const float4* __restrict__ pb = pa + PLANE / 4;     // next channel plane
        uint4* __restrict__ sd = reinterpret_cast<uint4*>(s);
        #pragma unroll
        for (int i = threadIdx.x; i < PLANE / 4; i += THREADS) {
            const float4 a = pa[i];
            const float4 b = pb[i];
            uint4 v;
            v.x = h2_bits(__floats2half2_rn(a.x, b.x));
            v.y = h2_bits(__floats2half2_rn(a.y, b.y));
            v.z = h2_bits(__floats2half2_rn(a.z, b.z));
            v.w = h2_bits(__floats2half2_rn(a.w, b.w));
            sd[i] = v;
        }
    }
    __syncthreads();

    const int t = threadIdx.x;

    // Paired phase: thread handles points 2t, 2t+1 (adjacent pix) per iter.
    // grid: one float4 = two float2 points, 16B aligned.
    const float4* __restrict__ g4 =
        reinterpret_cast<const float4*>(grid) + (size_t)n * (PTS / 2) + t;

    // out[n, p, c, hg, wg]  flat = ((n*98 + p)*128 + c)*256 + pix
    // pt = 2t: p = t>>7, pix = (2t)&255
    float* __restrict__ ob = out + (((size_t)n * 98) * CC + c0) * 256;
    float* __restrict__ o = ob + (t >> 7) * (CC * 256) + ((2 * t) & 255);

    #pragma unroll 4
    for (int i = 0; i < PAIR_ITERS; i++) {
        const float4 xy2 = g4[i * THREADS];      // points 2t, 2t+1

        const float xA = unnx(xy2.x), yA = unnx(xy2.y);
        const float xB = unnx(xy2.z), yB = unnx(xy2.w);

        const __half2 rA = bilerp_h2(s, xA, yA);
        const __half2 rB = bilerp_h2(s, xB, yB);

        const float2 fA = __half22float2(rA);
        const float2 fB = __half22float2(rB);

        // each iteration advances p by 1024/256 = 4 rows of [C,256]
        float* __restrict__ oi = o + i * (4 * CC * 256);
        // channel c0: adjacent pix -> one STG.64
        *reinterpret_cast<float2*>(oi)       = make_float2(fA.x, fB.x);
        // channel c0+1
        *reinterpret_cast<float2*>(oi + 256) = make_float2(fA.y, fB.y);
    }

    // Tail: last 512 points, one per thread. pt = 24576 + t.
    {
        const float2* __restrict__ g2 =
            reinterpret_cast<const float2*>(grid) + (size_t)n * PTS + 24576 + t;
        const float2 xy = *g2;
        const float x = unnx(xy.x), y = unnx(xy.y);
        const __half2 r = bilerp_h2(s, x, y);
        const float2 f = __half22float2(r);
        // p = (24576 + t) >> 8 = 96 + (t>>8), pix = t & 255
        float* __restrict__ ot = ob + (96 + (t >> 8)) * (CC * 256) + (t & 255);
        ot[0]   = f.x;
        ot[256] = f.y;
    }
}

extern "C" void kernel_launch(void* const* d_in, const int* in_sizes, int n_in,
                              void* d_out, int out_size)
{
    const float* fm   = (const float*)d_in[0];   // [16,128,112,112] f32
    const float* grid = (const float*)d_in[1];   // [16,98,16,16,2]  f32
    float* out        = (float*)d_out;           // [16,98,128,16,16] f32

    const int smem = PLANE * sizeof(__half2);    // 50,176 B
    cudaFuncSetAttribute(patches_kernel,
                         cudaFuncAttributeMaxDynamicSharedMemorySize, smem);

    const int blocks = NB * (CC / 2);            // 1024
    patches_kernel<<<blocks, THREADS, smem>>>(fm, grid, out);
}